// round 4
// baseline (speedup 1.0000x reference)
#include <cuda_runtime.h>

// DynamicHybridRouter: out = route(x @ gate_w^T + gate_b, expert_maturity)
// x: [M,2048] f32, gate_w: [64,2048] f32, gate_b: [64] f32, maturity: [64] i32
// all mature -> top-2 softmax scatter; any immature -> softmax(logits/2).

namespace {

constexpr int KDIM = 2048;
constexpr int NEXP = 64;
constexpr int BM = 128;      // rows per CTA
constexpr int BK = 32;       // K tile
constexpr int NTHREADS = 256;
constexpr int LG_STRIDE = 68;  // padded logits stride (avoids 32-way conflicts)
constexpr float TEMP_INV = 0.5f;  // 1/TEMPERATURE

typedef unsigned long long ull;

__device__ __forceinline__ ull pack2(float a, float b) {
    ull r;
    asm("mov.b64 %0, {%1, %2};" : "=l"(r)
        : "r"(__float_as_uint(a)), "r"(__float_as_uint(b)));
    return r;
}

__device__ __forceinline__ void unpack2(ull p, float& a, float& b) {
    unsigned lo, hi;
    asm("mov.b64 {%0, %1}, %2;" : "=r"(lo), "=r"(hi) : "l"(p));
    a = __uint_as_float(lo);
    b = __uint_as_float(hi);
}

// packed f32x2 fma (sm_100+): d.lo = a.lo*b.lo + c.lo ; d.hi = ...
__device__ __forceinline__ ull ffma2(ull a, ull b, ull c) {
    ull d;
    asm("fma.rn.f32x2 %0, %1, %2, %3;" : "=l"(d) : "l"(a), "l"(b), "l"(c));
    return d;
}

__global__ void __launch_bounds__(NTHREADS, 1)
router_kernel(const float* __restrict__ x,
              const float* __restrict__ gw,
              const float* __restrict__ gb,
              const int*   __restrict__ mat,
              float*       __restrict__ out)
{
    // SMEM union: GEMM tiles (xs: BK*BM = 4096 f, ws: BK*NEXP = 2048 f) then
    // logits tile (BM * LG_STRIDE = 8704 f = 34816 B).
    __shared__ __align__(16) float smem[BM * LG_STRIDE];
    float* xs = smem;            // [BK][BM], swizzled
    float* ws = smem + BK * BM;  // [BK][NEXP], swizzled

    const int tid = threadIdx.x;
    const int blockRow = blockIdx.x * BM;

    // Thread tile: 8 rows (4 f32x2 pairs) x 4 experts.
    const int eg = tid & 15;   // 16 expert groups
    const int rg = tid >> 4;   // 16 row groups
    const int e0 = eg * 4;     // expert base (mult of 4)
    const int r0 = rg * 8;     // row base (mult of 8)

    ull acc[4][4];
#pragma unroll
    for (int r = 0; r < 4; ++r)
#pragma unroll
        for (int e = 0; e < 4; ++e) acc[r][e] = 0ull;  // (0.f,0.f)

    const float* xBase = x + (size_t)blockRow * KDIM;

    float4 xr[4];
    float4 wr[2];

    // Prefetch tile 0 (global -> regs). Mapping: i = tid + p*256,
    // row = i>>3, k4 = i&7 -> 8 threads cover one 128B row segment (coalesced).
#pragma unroll
    for (int p = 0; p < 4; ++p) {
        int i = tid + p * NTHREADS;
        int row = i >> 3, k4 = i & 7;
        xr[p] = *(const float4*)(xBase + (size_t)row * KDIM + k4 * 4);
    }
#pragma unroll
    for (int p = 0; p < 2; ++p) {
        int i = tid + p * NTHREADS;
        int e = i >> 3, k4 = i & 7;
        wr[p] = *(const float4*)(gw + (size_t)e * KDIM + k4 * 4);
    }

    const int NT = KDIM / BK;
    for (int kt = 0; kt < NT; ++kt) {
        __syncthreads();  // prior compute done reading SMEM
        // Transposed store with XOR swizzle: element (k,row) lives at
        // k*BM + (row ^ (((k>>2)&7)*8)).  k4 = k>>2 within the tile.
#pragma unroll
        for (int p = 0; p < 4; ++p) {
            int i = tid + p * NTHREADS;
            int row = i >> 3, k4 = i & 7;
            int rsw = row ^ (k4 * 8);
            float4 v = xr[p];
            xs[(k4 * 4 + 0) * BM + rsw] = v.x;
            xs[(k4 * 4 + 1) * BM + rsw] = v.y;
            xs[(k4 * 4 + 2) * BM + rsw] = v.z;
            xs[(k4 * 4 + 3) * BM + rsw] = v.w;
        }
#pragma unroll
        for (int p = 0; p < 2; ++p) {
            int i = tid + p * NTHREADS;
            int e = i >> 3, k4 = i & 7;
            int esw = e ^ (k4 * 8);
            float4 v = wr[p];
            ws[(k4 * 4 + 0) * NEXP + esw] = v.x;
            ws[(k4 * 4 + 1) * NEXP + esw] = v.y;
            ws[(k4 * 4 + 2) * NEXP + esw] = v.z;
            ws[(k4 * 4 + 3) * NEXP + esw] = v.w;
        }
        __syncthreads();

        // Prefetch next tile while we compute on SMEM (hides GMEM latency).
        if (kt + 1 < NT) {
            int kOff = (kt + 1) * BK;
#pragma unroll
            for (int p = 0; p < 4; ++p) {
                int i = tid + p * NTHREADS;
                int row = i >> 3, k4 = i & 7;
                xr[p] = *(const float4*)(xBase + (size_t)row * KDIM + kOff + k4 * 4);
            }
#pragma unroll
            for (int p = 0; p < 2; ++p) {
                int i = tid + p * NTHREADS;
                int e = i >> 3, k4 = i & 7;
                wr[p] = *(const float4*)(gw + (size_t)e * KDIM + kOff + k4 * 4);
            }
        }

        // Compute: 32 k-steps, 16 FFMA2 each (8 rows x 4 experts).
#pragma unroll
        for (int k = 0; k < BK; ++k) {
            int s = ((k >> 2) & 7) * 8;
            const float* xp = &xs[k * BM + (r0 ^ s)];
            ulonglong2 xa = *(const ulonglong2*)xp;        // rows r0..r0+3
            ulonglong2 xb = *(const ulonglong2*)(xp + 4);  // rows r0+4..r0+7
            float4 wv = *(const float4*)&ws[k * NEXP + (e0 ^ s)];
            ull wp0 = pack2(wv.x, wv.x);
            ull wp1 = pack2(wv.y, wv.y);
            ull wp2 = pack2(wv.z, wv.z);
            ull wp3 = pack2(wv.w, wv.w);

            acc[0][0] = ffma2(xa.x, wp0, acc[0][0]);
            acc[0][1] = ffma2(xa.x, wp1, acc[0][1]);
            acc[0][2] = ffma2(xa.x, wp2, acc[0][2]);
            acc[0][3] = ffma2(xa.x, wp3, acc[0][3]);
            acc[1][0] = ffma2(xa.y, wp0, acc[1][0]);
            acc[1][1] = ffma2(xa.y, wp1, acc[1][1]);
            acc[1][2] = ffma2(xa.y, wp2, acc[1][2]);
            acc[1][3] = ffma2(xa.y, wp3, acc[1][3]);
            acc[2][0] = ffma2(xb.x, wp0, acc[2][0]);
            acc[2][1] = ffma2(xb.x, wp1, acc[2][1]);
            acc[2][2] = ffma2(xb.x, wp2, acc[2][2]);
            acc[2][3] = ffma2(xb.x, wp3, acc[2][3]);
            acc[3][0] = ffma2(xb.y, wp0, acc[3][0]);
            acc[3][1] = ffma2(xb.y, wp1, acc[3][1]);
            acc[3][2] = ffma2(xb.y, wp2, acc[3][2]);
            acc[3][3] = ffma2(xb.y, wp3, acc[3][3]);
        }
    }

    // ---------------- Epilogue: bias + routing ----------------
    int imm = 0;
    if (tid < NEXP) imm = (mat[tid] == 0) ? 1 : 0;
    int anyImm = __syncthreads_or(imm);  // barrier also protects SMEM reuse

    float b0 = gb[e0 + 0], b1 = gb[e0 + 1], b2 = gb[e0 + 2], b3 = gb[e0 + 3];
    float bb[4] = {b0, b1, b2, b3};

    // Scatter logits (+bias) into padded SMEM tile [BM][LG_STRIDE].
#pragma unroll
    for (int r = 0; r < 4; ++r) {
#pragma unroll
        for (int e = 0; e < 4; ++e) {
            float lo, hi;
            unpack2(acc[r][e], lo, hi);
            smem[(r0 + 2 * r + 0) * LG_STRIDE + e0 + e] = lo + bb[e];
            smem[(r0 + 2 * r + 1) * LG_STRIDE + e0 + e] = hi + bb[e];
        }
    }
    __syncthreads();

    if (tid < BM) {
        float* lrow = &smem[tid * LG_STRIDE];
        float* orow = out + (size_t)(blockRow + tid) * NEXP;

        if (!anyImm) {
            // top-2 (ties -> lower index, matching lax.top_k), softmax over 2
            float v1 = -3.4e38f, v2 = -3.4e38f;
            int i1 = 0, i2 = 0;
#pragma unroll
            for (int e = 0; e < NEXP; ++e) {
                float v = lrow[e];
                if (v > v1) { v2 = v1; i2 = i1; v1 = v; i1 = e; }
                else if (v > v2) { v2 = v; i2 = e; }
            }
            float t = __expf(v2 - v1);
            float inv = 1.0f / (1.0f + t);
            float w1 = inv;
            float w2 = t * inv;

            float4 z = make_float4(0.f, 0.f, 0.f, 0.f);
#pragma unroll
            for (int j = 0; j < NEXP / 4; ++j) ((float4*)orow)[j] = z;
            orow[i1] = w1;   // same-thread program order: overwrites the zero
            orow[i2] = w2;
        } else {
            // temperature softmax over all experts
            float mx = -3.4e38f;
#pragma unroll
            for (int e = 0; e < NEXP; ++e) mx = fmaxf(mx, lrow[e]);
            float sum = 0.f;
#pragma unroll
            for (int e = 0; e < NEXP; ++e) {
                float t = __expf((lrow[e] - mx) * TEMP_INV);
                lrow[e] = t;  // only this thread touches this row
                sum += t;
            }
            float inv = 1.0f / sum;
#pragma unroll
            for (int e = 0; e < NEXP; ++e) orow[e] = lrow[e] * inv;
        }
    }
}

}  // namespace

extern "C" void kernel_launch(void* const* d_in, const int* in_sizes, int n_in,
                              void* d_out, int out_size) {
    const float* x  = (const float*)d_in[0];
    const float* gw = (const float*)d_in[1];
    const float* gb = (const float*)d_in[2];
    const int*   mt = (const int*)d_in[3];
    float* out = (float*)d_out;

    const int M = in_sizes[0] / KDIM;   // 16384
    dim3 grid(M / BM);                  // 128 CTAs
    router_kernel<<<grid, NTHREADS>>>(x, gw, gb, mt, out);
}

// round 7
// speedup vs baseline: 1.2353x; 1.2353x over previous
#include <cuda_runtime.h>
#include <cstdint>

// DynamicHybridRouter via mma.sync tf32 3-product split (family-portable PTX;
// tcgen05 rejected: harness compiles at virtual target compute_103, not 103a).
//
// logits = x[M,2048] @ W^T[2048,64] + b; all-mature -> top-2 softmax scatter,
// any-immature -> softmax(logits/2).
//
// Precision: a = hi + lo, hi = cvt.rna.tf32(a), lo = cvt.rna.tf32(a - hi).
// D += Ahi*Bhi + Ahi*Blo + Alo*Bhi (fp32 accum). Dropped lo*lo ~ 2^-22 rel
// -> logit error ~2e-7, same class as the passing fp32 kernel.

namespace {

constexpr int KD = 2048;
constexpr int NEXP = 64;
constexpr int BM = 128;          // rows per CTA
constexpr int NT = KD / 32;      // 64 k-tiles of 32
constexpr int BSTR = 40;         // b-smem row stride in floats (conflict-free)
constexpr int BKIND = NEXP * BSTR;        // 2560 floats per (stage,kind)
constexpr int LGS = 68;                   // logits stride
constexpr int SM_FLOATS = 4 * BKIND + BM * LGS + 64;   // 19008
constexpr float TEMP_INV = 0.5f;

__device__ __forceinline__ uint32_t cvt_tf32(float v) {
    uint32_t r;
    asm("cvt.rna.tf32.f32 %0, %1;" : "=r"(r) : "f"(v));
    return r;
}

__device__ __forceinline__ void mma8(float* d, const uint32_t* a,
                                     const uint32_t* b) {
    asm volatile(
        "mma.sync.aligned.m16n8k8.row.col.f32.tf32.tf32.f32 "
        "{%0,%1,%2,%3}, {%4,%5,%6,%7}, {%8,%9}, {%0,%1,%2,%3};"
        : "+f"(d[0]), "+f"(d[1]), "+f"(d[2]), "+f"(d[3])
        : "r"(a[0]), "r"(a[1]), "r"(a[2]), "r"(a[3]),
          "r"(b[0]), "r"(b[1]));
}

__global__ void __launch_bounds__(256, 1)
router_mma(const float* __restrict__ x,
           const float* __restrict__ gw,
           const float* __restrict__ gb,
           const int*   __restrict__ mat,
           float*       __restrict__ out)
{
    extern __shared__ __align__(16) float sm[];
    float* lg    = sm + 4 * BKIND;            // [128][68]
    float* sbias = sm + 4 * BKIND + BM * LGS; // [64]

    const int tid = threadIdx.x;
    const int w   = tid >> 5;
    const int l   = tid & 31;
    const int fr  = l >> 2;     // fragment row-in-group / B n-in-group
    const int fc  = l & 3;      // fragment k index
    const int r0  = (w & 3) * 32;   // warp M slice
    const int kg  = w >> 2;         // k-group (0: k8 {0,1}, 1: k8 {2,3})
    const int blockRow = blockIdx.x * BM;

    // ---- maturity + bias ----
    int imm = 0;
    if (tid < NEXP) {
        imm = (mat[tid] == 0) ? 1 : 0;
        sbias[tid] = gb[tid];
    }
    const int anyImm = __syncthreads_or(imm);

    // ---- accumulators: 2 m16-tiles x 8 n8-tiles x 4 ----
    float acc[2][8][4];
#pragma unroll
    for (int mt = 0; mt < 2; ++mt)
#pragma unroll
        for (int nt = 0; nt < 8; ++nt)
#pragma unroll
            for (int q = 0; q < 4; ++q) acc[mt][nt][q] = 0.f;

    // ---- per-lane x base + fragment offsets ----
    const float* xlane = x + (size_t)(blockRow + r0 + fr) * KD + fc;
    const int offj[4] = {0, 8 * KD, 4, 8 * KD + 4};

    // ---- w tile staging (2 float4 per thread per k-tile) ----
    const int f0 = tid, f1 = tid + 256;
    const float* wp0 = gw + (f0 >> 3) * KD + (f0 & 7) * 4;
    const float* wp1 = gw + (f1 >> 3) * KD + (f1 & 7) * 4;
    float4 wv[2];
    wv[0] = *(const float4*)(wp0);
    wv[1] = *(const float4*)(wp1);

    // ---- A raw prefetch for tile 0 ----
    float rawc[2][8], rawn[2][8];
#pragma unroll
    for (int i = 0; i < 2; ++i) {
        int ko = kg * 16 + i * 8;
#pragma unroll
        for (int mt = 0; mt < 2; ++mt)
#pragma unroll
            for (int j = 0; j < 4; ++j)
                rawc[i][mt * 4 + j] = xlane[mt * 16 * KD + offj[j] + ko];
    }

    for (int kt = 0; kt < NT; ++kt) {
        const int s = kt & 1;
        float* bh = sm + (s * 2 + 0) * BKIND;
        float* bl = sm + (s * 2 + 1) * BKIND;

        // ---- convert + store w tile kt into buf s (k-permuted) ----
#pragma unroll
        for (int q = 0; q < 2; ++q) {
            int f = tid + q * 256;
            int kq4 = f & 7;
            int base = (f >> 3) * BSTR + (kq4 >> 1) * 8 + (kq4 & 1);
            float vv[4] = {wv[q].x, wv[q].y, wv[q].z, wv[q].w};
#pragma unroll
            for (int j = 0; j < 4; ++j) {
                uint32_t h = cvt_tf32(vv[j]);
                uint32_t lo = cvt_tf32(vv[j] - __uint_as_float(h));
                bh[base + 2 * j] = __uint_as_float(h);
                bl[base + 2 * j] = __uint_as_float(lo);
            }
        }
        __syncthreads();

        // ---- prefetch next w tile + next A raw ----
        if (kt + 1 < NT) {
            wv[0] = *(const float4*)(wp0 + (kt + 1) * 32);
            wv[1] = *(const float4*)(wp1 + (kt + 1) * 32);
#pragma unroll
            for (int i = 0; i < 2; ++i) {
                int ko = (kt + 1) * 32 + kg * 16 + i * 8;
#pragma unroll
                for (int mt = 0; mt < 2; ++mt)
#pragma unroll
                    for (int j = 0; j < 4; ++j)
                        rawn[i][mt * 4 + j] =
                            xlane[mt * 16 * KD + offj[j] + ko];
            }
        }

        // ---- compute 2 k8 steps from buf s ----
#pragma unroll
        for (int i = 0; i < 2; ++i) {
            const int lk8 = kg * 2 + i;

            uint32_t ahi[2][4], alo[2][4];
#pragma unroll
            for (int mt = 0; mt < 2; ++mt)
#pragma unroll
                for (int j = 0; j < 4; ++j) {
                    float v = rawc[i][mt * 4 + j];
                    uint32_t h = cvt_tf32(v);
                    ahi[mt][j] = h;
                    alo[mt][j] = cvt_tf32(v - __uint_as_float(h));
                }

            uint32_t bhf[8][2], blf[8][2];
#pragma unroll
            for (int nt = 0; nt < 8; ++nt) {
                int idx = (nt * 8 + fr) * BSTR + lk8 * 8 + fc * 2;
                float2 h2 = *(const float2*)&bh[idx];
                float2 l2 = *(const float2*)&bl[idx];
                bhf[nt][0] = __float_as_uint(h2.x);
                bhf[nt][1] = __float_as_uint(h2.y);
                blf[nt][0] = __float_as_uint(l2.x);
                blf[nt][1] = __float_as_uint(l2.y);
            }

            // product-major: dep distance 16 mma >> HMMA latency
#pragma unroll
            for (int nt = 0; nt < 8; ++nt)
#pragma unroll
                for (int mt = 0; mt < 2; ++mt)
                    mma8(acc[mt][nt], ahi[mt], bhf[nt]);
#pragma unroll
            for (int nt = 0; nt < 8; ++nt)
#pragma unroll
                for (int mt = 0; mt < 2; ++mt)
                    mma8(acc[mt][nt], ahi[mt], blf[nt]);
#pragma unroll
            for (int nt = 0; nt < 8; ++nt)
#pragma unroll
                for (int mt = 0; mt < 2; ++mt)
                    mma8(acc[mt][nt], alo[mt], bhf[nt]);
        }

        // rotate A raw buffers
#pragma unroll
        for (int i = 0; i < 2; ++i)
#pragma unroll
            for (int j = 0; j < 8; ++j) rawc[i][j] = rawn[i][j];
    }

    // ---- k-split reduction into logits smem ----
    if (w >= 4) {
#pragma unroll
        for (int mt = 0; mt < 2; ++mt)
#pragma unroll
            for (int nt = 0; nt < 8; ++nt) {
                int row = r0 + mt * 16 + fr;
                int e = nt * 8 + fc * 2;
                *(float2*)&lg[row * LGS + e] =
                    make_float2(acc[mt][nt][0], acc[mt][nt][1]);
                *(float2*)&lg[(row + 8) * LGS + e] =
                    make_float2(acc[mt][nt][2], acc[mt][nt][3]);
            }
    }
    __syncthreads();
    if (w < 4) {
#pragma unroll
        for (int mt = 0; mt < 2; ++mt)
#pragma unroll
            for (int nt = 0; nt < 8; ++nt) {
                int row = r0 + mt * 16 + fr;
                int e = nt * 8 + fc * 2;
                float2 bv = *(const float2*)&sbias[e];
                float2 o0 = *(float2*)&lg[row * LGS + e];
                o0.x += acc[mt][nt][0] + bv.x;
                o0.y += acc[mt][nt][1] + bv.y;
                *(float2*)&lg[row * LGS + e] = o0;
                float2 o1 = *(float2*)&lg[(row + 8) * LGS + e];
                o1.x += acc[mt][nt][2] + bv.x;
                o1.y += acc[mt][nt][3] + bv.y;
                *(float2*)&lg[(row + 8) * LGS + e] = o1;
            }
    }
    __syncthreads();

    // ---- routing epilogue (identical to the passing round-4 kernel) ----
    if (tid < BM) {
        float* lrow = &lg[tid * LGS];
        float* orow = out + (size_t)(blockRow + tid) * NEXP;

        if (!anyImm) {
            float v1 = -3.4e38f, v2 = -3.4e38f;
            int i1 = 0, i2 = 0;
#pragma unroll
            for (int e = 0; e < NEXP; ++e) {
                float v = lrow[e];
                if (v > v1) { v2 = v1; i2 = i1; v1 = v; i1 = e; }
                else if (v > v2) { v2 = v; i2 = e; }
            }
            float t = __expf(v2 - v1);
            float inv = 1.0f / (1.0f + t);
            float4 z = make_float4(0.f, 0.f, 0.f, 0.f);
#pragma unroll
            for (int j = 0; j < NEXP / 4; ++j) ((float4*)orow)[j] = z;
            orow[i1] = inv;
            orow[i2] = t * inv;
        } else {
            float mx = -3.4e38f;
#pragma unroll
            for (int e = 0; e < NEXP; ++e) mx = fmaxf(mx, lrow[e]);
            float sum = 0.f;
#pragma unroll
            for (int e = 0; e < NEXP; ++e) {
                float t = __expf((lrow[e] - mx) * TEMP_INV);
                lrow[e] = t;
                sum += t;
            }
            float inv = 1.0f / sum;
#pragma unroll
            for (int e = 0; e < NEXP; ++e) orow[e] = lrow[e] * inv;
        }
    }
}

}  // namespace

extern "C" void kernel_launch(void* const* d_in, const int* in_sizes, int n_in,
                              void* d_out, int out_size) {
    const float* x  = (const float*)d_in[0];
    const float* gw = (const float*)d_in[1];
    const float* gb = (const float*)d_in[2];
    const int*   mt = (const int*)d_in[3];
    float* out = (float*)d_out;

    const int M = in_sizes[0] / KD;     // 16384
    const int smem = SM_FLOATS * (int)sizeof(float);   // 76032 B
    cudaFuncSetAttribute(router_mma,
                         cudaFuncAttributeMaxDynamicSharedMemorySize, smem);
    router_mma<<<M / BM, 256, smem>>>(x, gw, gb, mt, out);
}

// round 8
// speedup vs baseline: 1.8016x; 1.4585x over previous
#include <cuda_runtime.h>
#include <cuda_fp16.h>
#include <cstdint>

// DynamicHybridRouter via mma.sync fp16 3-product split GEMM.
// logits = x[M,2048] @ W^T[2048,64] + b; all-mature -> top-2 softmax scatter,
// any-immature -> softmax(logits/2).
//
// Precision: a = hi + lo/2048 with hi = f16_rn(a), lo = f16_rn((a-hi)*2048).
// acc1 += ahi*bhi ; acc2 += ahi*blo + alo*bhi (both fp32 accum); logits =
// acc1 + acc2/2048. Dropped lo*lo term ~2^-24 rel -> logit err ~2e-7.
//
// W (512KB, L2-resident) is pre-packed once per launch into a fragment-native
// layout so the main loop needs no SMEM staging and no __syncthreads.

constexpr int KD = 2048;
constexpr int NEXP = 64;
constexpr int BM = 128;
constexpr int NT = KD / 32;          // 64 k-tiles; 1 k16-step per warp each
constexpr int LGS = 68;
constexpr float TEMP_INV = 0.5f;
constexpr float LO_SCALE = 2048.0f;
constexpr float LO_INV = 1.0f / 2048.0f;

// [k16=128][e=64][fc=4] -> uint4 {hi(k=2fc,2fc+1), hi(2fc+8,2fc+9),
//                                 lo(2fc,2fc+1),   lo(2fc+8,2fc+9)}
// (k within a k16 step is permuted g(j)=2*(j&3)+(j>>2), applied identically
//  to A, so the contraction is unchanged.)
__device__ uint4 g_wpack[128 * 64 * 4];

__device__ __forceinline__ uint32_t h2u(__half2 h) {
    return *reinterpret_cast<uint32_t*>(&h);
}

__global__ void __launch_bounds__(256) pack_w_kernel(const float* __restrict__ gw) {
    int i = blockIdx.x * 256 + threadIdx.x;     // 32768 items
    int fc = i & 3, e = (i >> 2) & 63, k16 = i >> 8;
    const float* p = gw + e * KD + k16 * 16 + 2 * fc;
    float2 v0 = make_float2(p[0], p[1]);
    float2 v8 = make_float2(p[8], p[9]);
    __half2 h0 = __float22half2_rn(v0);
    __half2 h8 = __float22half2_rn(v8);
    float2 f0 = __half22float2(h0);
    float2 f8 = __half22float2(h8);
    __half2 l0 = __float22half2_rn(
        make_float2((v0.x - f0.x) * LO_SCALE, (v0.y - f0.y) * LO_SCALE));
    __half2 l8 = __float22half2_rn(
        make_float2((v8.x - f8.x) * LO_SCALE, (v8.y - f8.y) * LO_SCALE));
    uint4 q;
    q.x = h2u(h0); q.y = h2u(h8); q.z = h2u(l0); q.w = h2u(l8);
    g_wpack[i] = q;
}

__device__ __forceinline__ void mma16(float* d, const uint32_t* a,
                                      uint32_t b0, uint32_t b1) {
    asm volatile(
        "mma.sync.aligned.m16n8k16.row.col.f32.f16.f16.f32 "
        "{%0,%1,%2,%3}, {%4,%5,%6,%7}, {%8,%9}, {%0,%1,%2,%3};"
        : "+f"(d[0]), "+f"(d[1]), "+f"(d[2]), "+f"(d[3])
        : "r"(a[0]), "r"(a[1]), "r"(a[2]), "r"(a[3]), "r"(b0), "r"(b1));
}

__global__ void __launch_bounds__(256, 1)
router_fp16(const float* __restrict__ x,
            const float* __restrict__ gb,
            const int*   __restrict__ mat,
            float*       __restrict__ out)
{
    __shared__ __align__(16) float lg[BM * LGS + NEXP];
    float* sbias = lg + BM * LGS;

    const int tid = threadIdx.x;
    const int w   = tid >> 5;
    const int l   = tid & 31;
    const int fr  = l >> 2;           // A row-in-group / B n-in-group
    const int fc  = l & 3;            // fragment k quad
    const int r0  = (w & 3) * 32;     // warp M slice
    const int kg  = w >> 2;           // k16 parity (warp k-split)
    const int blockRow = blockIdx.x * BM;

    int imm = 0;
    if (tid < NEXP) {
        imm = (mat[tid] == 0) ? 1 : 0;
        sbias[tid] = gb[tid];
    }
    const int anyImm = __syncthreads_or(imm);

    float acc1[2][8][4], acc2[2][8][4];
#pragma unroll
    for (int mt = 0; mt < 2; ++mt)
#pragma unroll
        for (int nt = 0; nt < 8; ++nt)
#pragma unroll
            for (int q = 0; q < 4; ++q) { acc1[mt][nt][q] = 0.f; acc2[mt][nt][q] = 0.f; }

    // per-lane A base: row (blockRow + r0 + fr), k offset kg*16 + 2*fc
    const float* xb = x + (size_t)(blockRow + r0 + fr) * KD + kg * 16 + 2 * fc;

    // raw A: [mt*4 + rh*2 + kp] ; row = r0 + mt*16 + rh*8 + fr,
    // k = tile_ko + kp*8 + {0,1}
    float2 rawc[8], rawn[8];
#pragma unroll
    for (int mt = 0; mt < 2; ++mt)
#pragma unroll
        for (int rh = 0; rh < 2; ++rh)
#pragma unroll
            for (int kp = 0; kp < 2; ++kp)
                rawc[mt * 4 + rh * 2 + kp] =
                    *(const float2*)(xb + (size_t)(mt * 16 + rh * 8) * KD + kp * 8);

    for (int kt = 0; kt < NT; ++kt) {
        // ---- B fragments for this warp's k16 step (L1/L2) ----
        const uint4* wt = g_wpack + (size_t)(kt * 2 + kg) * 256 + fr * 4 + fc;
        uint4 bq[8];
#pragma unroll
        for (int nt = 0; nt < 8; ++nt) bq[nt] = wt[nt * 32];

        // ---- prefetch next tile's A (DRAM latency hidden under mma) ----
        if (kt + 1 < NT) {
            const float* xt = xb + (kt + 1) * 32;
#pragma unroll
            for (int mt = 0; mt < 2; ++mt)
#pragma unroll
                for (int rh = 0; rh < 2; ++rh)
#pragma unroll
                    for (int kp = 0; kp < 2; ++kp)
                        rawn[mt * 4 + rh * 2 + kp] =
                            *(const float2*)(xt + (size_t)(mt * 16 + rh * 8) * KD + kp * 8);
        }

        // ---- A hi/lo fp16 fragments ----
        uint32_t ahi[2][4], alo[2][4];
#pragma unroll
        for (int mt = 0; mt < 2; ++mt)
#pragma unroll
            for (int rh = 0; rh < 2; ++rh)
#pragma unroll
                for (int kp = 0; kp < 2; ++kp) {
                    float2 v = rawc[mt * 4 + rh * 2 + kp];
                    __half2 h = __float22half2_rn(v);
                    float2 f = __half22float2(h);
                    __half2 lo2 = __float22half2_rn(make_float2(
                        (v.x - f.x) * LO_SCALE, (v.y - f.y) * LO_SCALE));
                    // a0:rh0,kp0  a1:rh1,kp0  a2:rh0,kp1  a3:rh1,kp1
                    ahi[mt][kp * 2 + rh] = h2u(h);
                    alo[mt][kp * 2 + rh] = h2u(lo2);
                }

        // ---- 48 mma, product-major (acc dep distance = 16) ----
#pragma unroll
        for (int nt = 0; nt < 8; ++nt)
#pragma unroll
            for (int mt = 0; mt < 2; ++mt)
                mma16(acc1[mt][nt], ahi[mt], bq[nt].x, bq[nt].y);
#pragma unroll
        for (int nt = 0; nt < 8; ++nt)
#pragma unroll
            for (int mt = 0; mt < 2; ++mt)
                mma16(acc2[mt][nt], ahi[mt], bq[nt].z, bq[nt].w);
#pragma unroll
        for (int nt = 0; nt < 8; ++nt)
#pragma unroll
            for (int mt = 0; mt < 2; ++mt)
                mma16(acc2[mt][nt], alo[mt], bq[nt].x, bq[nt].y);

#pragma unroll
        for (int j = 0; j < 8; ++j) rawc[j] = rawn[j];
    }

    // ---- k-split reduction into logits SMEM (combine acc1 + acc2/2048) ----
    if (w >= 4) {
#pragma unroll
        for (int mt = 0; mt < 2; ++mt)
#pragma unroll
            for (int nt = 0; nt < 8; ++nt) {
                int row = r0 + mt * 16 + fr;
                int e = nt * 8 + fc * 2;
                *(float2*)&lg[row * LGS + e] = make_float2(
                    fmaf(acc2[mt][nt][0], LO_INV, acc1[mt][nt][0]),
                    fmaf(acc2[mt][nt][1], LO_INV, acc1[mt][nt][1]));
                *(float2*)&lg[(row + 8) * LGS + e] = make_float2(
                    fmaf(acc2[mt][nt][2], LO_INV, acc1[mt][nt][2]),
                    fmaf(acc2[mt][nt][3], LO_INV, acc1[mt][nt][3]));
            }
    }
    __syncthreads();
    if (w < 4) {
#pragma unroll
        for (int mt = 0; mt < 2; ++mt)
#pragma unroll
            for (int nt = 0; nt < 8; ++nt) {
                int row = r0 + mt * 16 + fr;
                int e = nt * 8 + fc * 2;
                float2 bv = *(const float2*)&sbias[e];
                float2 o0 = *(float2*)&lg[row * LGS + e];
                o0.x += fmaf(acc2[mt][nt][0], LO_INV, acc1[mt][nt][0]) + bv.x;
                o0.y += fmaf(acc2[mt][nt][1], LO_INV, acc1[mt][nt][1]) + bv.y;
                *(float2*)&lg[row * LGS + e] = o0;
                float2 o1 = *(float2*)&lg[(row + 8) * LGS + e];
                o1.x += fmaf(acc2[mt][nt][2], LO_INV, acc1[mt][nt][2]) + bv.x;
                o1.y += fmaf(acc2[mt][nt][3], LO_INV, acc1[mt][nt][3]) + bv.y;
                *(float2*)&lg[(row + 8) * LGS + e] = o1;
            }
    }
    __syncthreads();

    // ---- routing epilogue (identical to the passing kernels) ----
    if (tid < BM) {
        float* lrow = &lg[tid * LGS];
        float* orow = out + (size_t)(blockRow + tid) * NEXP;

        if (!anyImm) {
            float v1 = -3.4e38f, v2 = -3.4e38f;
            int i1 = 0, i2 = 0;
#pragma unroll
            for (int e = 0; e < NEXP; ++e) {
                float v = lrow[e];
                if (v > v1) { v2 = v1; i2 = i1; v1 = v; i1 = e; }
                else if (v > v2) { v2 = v; i2 = e; }
            }
            float t = __expf(v2 - v1);
            float inv = 1.0f / (1.0f + t);
            float4 z = make_float4(0.f, 0.f, 0.f, 0.f);
#pragma unroll
            for (int j = 0; j < NEXP / 4; ++j) ((float4*)orow)[j] = z;
            orow[i1] = inv;
            orow[i2] = t * inv;
        } else {
            float mx = -3.4e38f;
#pragma unroll
            for (int e = 0; e < NEXP; ++e) mx = fmaxf(mx, lrow[e]);
            float sum = 0.f;
#pragma unroll
            for (int e = 0; e < NEXP; ++e) {
                float t = __expf((lrow[e] - mx) * TEMP_INV);
                lrow[e] = t;
                sum += t;
            }
            float inv = 1.0f / sum;
#pragma unroll
            for (int e = 0; e < NEXP; ++e) orow[e] = lrow[e] * inv;
        }
    }
}

extern "C" void kernel_launch(void* const* d_in, const int* in_sizes, int n_in,
                              void* d_out, int out_size) {
    const float* x  = (const float*)d_in[0];
    const float* gw = (const float*)d_in[1];
    const float* gb = (const float*)d_in[2];
    const int*   mt = (const int*)d_in[3];
    float* out = (float*)d_out;

    const int M = in_sizes[0] / KD;     // 16384
    pack_w_kernel<<<128, 256>>>(gw);
    router_fp16<<<M / BM, 256>>>(x, gb, mt, out);
}

// round 9
// speedup vs baseline: 2.2463x; 1.2469x over previous
#include <cuda_runtime.h>
#include <cuda_fp16.h>
#include <cstdint>

// DynamicHybridRouter via mma.sync fp16 3-product split GEMM.
// logits = x[M,2048] @ W^T[2048,64] + b; all-mature -> top-2 softmax scatter,
// any-immature -> softmax(logits/2).
//
// Precision: a = hi + lo/2048, hi = f16_rn(a), lo = f16_rn((a-hi)*2048).
// acc1 += ahi*bhi ; acc2 += ahi*blo + alo*bhi ; logits = acc1 + acc2/2048.
// Dropped lo*lo ~2^-24 rel -> logit err ~2e-7.
//
// R8 layout: 512 thr / 16 warps per CTA (8 M-slices x 2 k-groups), 64 acc
// regs per thread -> 16-warp residency; A prefetch distance 2.

constexpr int KD = 2048;
constexpr int NEXP = 64;
constexpr int BM = 128;
constexpr int NT = KD / 32;          // 64 k-tiles; 1 k16 step per warp each
constexpr int LGS = 68;
constexpr float TEMP_INV = 0.5f;
constexpr float LO_SCALE = 2048.0f;
constexpr float LO_INV = 1.0f / 2048.0f;

// [k16=128][e=64][fc=4] -> uint4 {hi(k=2fc,2fc+1), hi(2fc+8,2fc+9),
//                                 lo(2fc,2fc+1),   lo(2fc+8,2fc+9)}
__device__ uint4 g_wpack[128 * 64 * 4];

__device__ __forceinline__ uint32_t h2u(__half2 h) {
    return *reinterpret_cast<uint32_t*>(&h);
}

__global__ void __launch_bounds__(256) pack_w_kernel(const float* __restrict__ gw) {
    int i = blockIdx.x * 256 + threadIdx.x;     // 32768 items
    int fc = i & 3, e = (i >> 2) & 63, k16 = i >> 8;
    const float* p = gw + e * KD + k16 * 16 + 2 * fc;
    float2 v0 = make_float2(p[0], p[1]);
    float2 v8 = make_float2(p[8], p[9]);
    __half2 h0 = __float22half2_rn(v0);
    __half2 h8 = __float22half2_rn(v8);
    float2 f0 = __half22float2(h0);
    float2 f8 = __half22float2(h8);
    __half2 l0 = __float22half2_rn(
        make_float2((v0.x - f0.x) * LO_SCALE, (v0.y - f0.y) * LO_SCALE));
    __half2 l8 = __float22half2_rn(
        make_float2((v8.x - f8.x) * LO_SCALE, (v8.y - f8.y) * LO_SCALE));
    uint4 q;
    q.x = h2u(h0); q.y = h2u(h8); q.z = h2u(l0); q.w = h2u(l8);
    g_wpack[i] = q;
}

__device__ __forceinline__ void mma16(float* d, const uint32_t* a,
                                      uint32_t b0, uint32_t b1) {
    asm volatile(
        "mma.sync.aligned.m16n8k16.row.col.f32.f16.f16.f32 "
        "{%0,%1,%2,%3}, {%4,%5,%6,%7}, {%8,%9}, {%0,%1,%2,%3};"
        : "+f"(d[0]), "+f"(d[1]), "+f"(d[2]), "+f"(d[3])
        : "r"(a[0]), "r"(a[1]), "r"(a[2]), "r"(a[3]), "r"(b0), "r"(b1));
}

__device__ __forceinline__ void cvt_hilo(float2 v, uint32_t& hi, uint32_t& lo) {
    __half2 h = __float22half2_rn(v);
    float2 f = __half22float2(h);
    __half2 l2 = __float22half2_rn(
        make_float2((v.x - f.x) * LO_SCALE, (v.y - f.y) * LO_SCALE));
    hi = h2u(h);
    lo = h2u(l2);
}

__global__ void __launch_bounds__(512, 1)
router_fp16(const float* __restrict__ x,
            const float* __restrict__ gb,
            const int*   __restrict__ mat,
            float*       __restrict__ out)
{
    __shared__ __align__(16) float lg[BM * LGS + NEXP];
    float* sbias = lg + BM * LGS;

    const int tid = threadIdx.x;
    const int w   = tid >> 5;
    const int l   = tid & 31;
    const int fr  = l >> 2;           // A row-in-group / B n-in-group
    const int fc  = l & 3;            // fragment k quad
    const int ms  = w & 7;            // M slice (16 rows)
    const int kg  = w >> 3;           // k16 half of each 32-k tile
    const int blockRow = blockIdx.x * BM;

    int imm = 0;
    if (tid < NEXP) {
        imm = (mat[tid] == 0) ? 1 : 0;
        sbias[tid] = gb[tid];
    }
    const int anyImm = __syncthreads_or(imm);

    float acc1[8][4], acc2[8][4];
#pragma unroll
    for (int nt = 0; nt < 8; ++nt)
#pragma unroll
        for (int q = 0; q < 4; ++q) { acc1[nt][q] = 0.f; acc2[nt][q] = 0.f; }

    // per-lane A base: row (blockRow + ms*16 + fr), k offset kg*16 + 2*fc
    const float* xb = x + (size_t)(blockRow + ms * 16 + fr) * KD + kg * 16 + 2 * fc;

    // raw A stages: [rh*2 + kp], rh = row half (+8 rows), kp = k half (+8 k)
    float2 raw0[4], raw1[4], raw2[4];
#pragma unroll
    for (int rh = 0; rh < 2; ++rh)
#pragma unroll
        for (int kp = 0; kp < 2; ++kp) {
            raw0[rh * 2 + kp] = *(const float2*)(xb + (size_t)(rh * 8) * KD + kp * 8);
            raw1[rh * 2 + kp] = *(const float2*)(xb + (size_t)(rh * 8) * KD + kp * 8 + 32);
        }

    const uint4* wbase = g_wpack + (size_t)kg * 256 + fr * 4 + fc;

#pragma unroll 4
    for (int kt = 0; kt < NT; ++kt) {
        // ---- prefetch A for kt+2 (covers DRAM latency across 2 tiles) ----
        if (kt + 2 < NT) {
            const float* xt = xb + (kt + 2) * 32;
#pragma unroll
            for (int rh = 0; rh < 2; ++rh)
#pragma unroll
                for (int kp = 0; kp < 2; ++kp)
                    raw2[rh * 2 + kp] =
                        *(const float2*)(xt + (size_t)(rh * 8) * KD + kp * 8);
        }

        const uint4* wt = wbase + (size_t)(kt * 2) * 256;

        // ---- A hi/lo fragments for current tile ----
        uint32_t ahi[4], alo[4];
#pragma unroll
        for (int rh = 0; rh < 2; ++rh)
#pragma unroll
            for (int kp = 0; kp < 2; ++kp)
                cvt_hilo(raw0[rh * 2 + kp], ahi[kp * 2 + rh], alo[kp * 2 + rh]);

        // ---- first half: experts 0..31 (4 n8 tiles) ----
        {
            uint4 bq[4];
#pragma unroll
            for (int nt = 0; nt < 4; ++nt) bq[nt] = wt[nt * 32];
#pragma unroll
            for (int nt = 0; nt < 4; ++nt) mma16(acc1[nt], ahi, bq[nt].x, bq[nt].y);
#pragma unroll
            for (int nt = 0; nt < 4; ++nt) mma16(acc2[nt], ahi, bq[nt].z, bq[nt].w);
#pragma unroll
            for (int nt = 0; nt < 4; ++nt) mma16(acc2[nt], alo, bq[nt].x, bq[nt].y);
        }
        // ---- second half: experts 32..63 ----
        {
            uint4 bq[4];
#pragma unroll
            for (int nt = 0; nt < 4; ++nt) bq[nt] = wt[(nt + 4) * 32];
#pragma unroll
            for (int nt = 0; nt < 4; ++nt) mma16(acc1[nt + 4], ahi, bq[nt].x, bq[nt].y);
#pragma unroll
            for (int nt = 0; nt < 4; ++nt) mma16(acc2[nt + 4], ahi, bq[nt].z, bq[nt].w);
#pragma unroll
            for (int nt = 0; nt < 4; ++nt) mma16(acc2[nt + 4], alo, bq[nt].x, bq[nt].y);
        }

        // rotate A stages
#pragma unroll
        for (int j = 0; j < 4; ++j) { raw0[j] = raw1[j]; raw1[j] = raw2[j]; }
    }

    // ---- k-split reduction into logits SMEM ----
    if (kg == 1) {
#pragma unroll
        for (int nt = 0; nt < 8; ++nt) {
            int row = ms * 16 + fr;
            int e = nt * 8 + fc * 2;
            *(float2*)&lg[row * LGS + e] = make_float2(
                fmaf(acc2[nt][0], LO_INV, acc1[nt][0]),
                fmaf(acc2[nt][1], LO_INV, acc1[nt][1]));
            *(float2*)&lg[(row + 8) * LGS + e] = make_float2(
                fmaf(acc2[nt][2], LO_INV, acc1[nt][2]),
                fmaf(acc2[nt][3], LO_INV, acc1[nt][3]));
        }
    }
    __syncthreads();
    if (kg == 0) {
#pragma unroll
        for (int nt = 0; nt < 8; ++nt) {
            int row = ms * 16 + fr;
            int e = nt * 8 + fc * 2;
            float2 bv = *(const float2*)&sbias[e];
            float2 o0 = *(float2*)&lg[row * LGS + e];
            o0.x += fmaf(acc2[nt][0], LO_INV, acc1[nt][0]) + bv.x;
            o0.y += fmaf(acc2[nt][1], LO_INV, acc1[nt][1]) + bv.y;
            *(float2*)&lg[row * LGS + e] = o0;
            float2 o1 = *(float2*)&lg[(row + 8) * LGS + e];
            o1.x += fmaf(acc2[nt][2], LO_INV, acc1[nt][2]) + bv.x;
            o1.y += fmaf(acc2[nt][3], LO_INV, acc1[nt][3]) + bv.y;
            *(float2*)&lg[(row + 8) * LGS + e] = o1;
        }
    }
    __syncthreads();

    // ---- routing epilogue (identical to the passing kernels) ----
    if (tid < BM) {
        float* lrow = &lg[tid * LGS];
        float* orow = out + (size_t)(blockRow + tid) * NEXP;

        if (!anyImm) {
            float v1 = -3.4e38f, v2 = -3.4e38f;
            int i1 = 0, i2 = 0;
#pragma unroll
            for (int e = 0; e < NEXP; ++e) {
                float v = lrow[e];
                if (v > v1) { v2 = v1; i2 = i1; v1 = v; i1 = e; }
                else if (v > v2) { v2 = v; i2 = e; }
            }
            float t = __expf(v2 - v1);
            float inv = 1.0f / (1.0f + t);
            float4 z = make_float4(0.f, 0.f, 0.f, 0.f);
#pragma unroll
            for (int j = 0; j < NEXP / 4; ++j) ((float4*)orow)[j] = z;
            orow[i1] = inv;
            orow[i2] = t * inv;
        } else {
            float mx = -3.4e38f;
#pragma unroll
            for (int e = 0; e < NEXP; ++e) mx = fmaxf(mx, lrow[e]);
            float sum = 0.f;
#pragma unroll
            for (int e = 0; e < NEXP; ++e) {
                float t = __expf((lrow[e] - mx) * TEMP_INV);
                lrow[e] = t;
                sum += t;
            }
            float inv = 1.0f / sum;
#pragma unroll
            for (int e = 0; e < NEXP; ++e) orow[e] = lrow[e] * inv;
        }
    }
}

extern "C" void kernel_launch(void* const* d_in, const int* in_sizes, int n_in,
                              void* d_out, int out_size) {
    const float* x  = (const float*)d_in[0];
    const float* gw = (const float*)d_in[1];
    const float* gb = (const float*)d_in[2];
    const int*   mt = (const int*)d_in[3];
    float* out = (float*)d_out;

    const int M = in_sizes[0] / KD;     // 16384
    pack_w_kernel<<<128, 256>>>(gw);
    router_fp16<<<M / BM, 512>>>(x, gb, mt, out);
}